// round 2
// baseline (speedup 1.0000x reference)
#include <cuda_runtime.h>
#include <cuda_bf16.h>

// Problem dims (fixed per reference)
#define N_NODES 1024
#define EDIM 16
#define NDIM 32

// ---------------- constant weights ----------------
__constant__ float cWe1[96 * 16];   // rows 0..31: A part, 32..63: B part, 64..95: edge part
__constant__ float cbe1[16];
__constant__ float cWe2[16 * 16];
__constant__ float cbe2[16];
__constant__ float cWn1[48 * 32];
__constant__ float cbn1[32];
__constant__ float cWn2[32 * 32];
__constant__ float cbn2[32];

// ---------------- device scratch ----------------
__device__ float g_pa[N_NODES * EDIM];     // a @ We1[0:32] + be1
__device__ float g_pb[N_NODES * EDIM];     // b @ We1[32:64]
__device__ float g_msga[N_NODES * EDIM];   // sum over j of new_edges[i,j,:]
__device__ float g_msgb[N_NODES * EDIM];   // sum over i of new_edges[i,j,:]

// ============ Kernel A: zero accumulators + per-node precompute ============
__global__ __launch_bounds__(256) void prep_kernel(const float* __restrict__ na,
                                                   const float* __restrict__ nb) {
    int node = blockIdx.x * blockDim.x + threadIdx.x;
    if (node >= N_NODES) return;

#pragma unroll
    for (int c = 0; c < 16; c++) {
        g_msga[node * 16 + c] = 0.0f;
        g_msgb[node * 16 + c] = 0.0f;
    }

    float xa[32], xb[32];
#pragma unroll
    for (int k = 0; k < 32; k++) {
        xa[k] = na[node * 32 + k];
        xb[k] = nb[node * 32 + k];
    }
#pragma unroll
    for (int c = 0; c < 16; c++) {
        float sa = cbe1[c];
        float sb = 0.0f;
#pragma unroll
        for (int k = 0; k < 32; k++) {
            sa += xa[k] * cWe1[k * 16 + c];
            sb += xb[k] * cWe1[(32 + k) * 16 + c];
        }
        g_pa[node * 16 + c] = sa;
        g_pb[node * 16 + c] = sb;
    }
}

// Butterfly channel-merging reduction: reduces 16 per-lane channel values
// across the 32 lanes of a warp in 16 shfls. On return, lanes 0..15 hold the
// full warp sum of channel chan16(lane).
__device__ __forceinline__ int chan16(int lane) {
    return ((lane & 1) ? 8 : 0) | ((lane & 2) ? 4 : 0) |
           ((lane & 4) ? 2 : 0) | ((lane & 8) ? 1 : 0);
}

__device__ __forceinline__ float warp_reduce16(float* v, int lane) {
    const unsigned FULL = 0xffffffffu;
    // step m=1: 16 -> 8
    {
        bool hi = (lane & 1);
#pragma unroll
        for (int k = 0; k < 8; k++) {
            float send  = hi ? v[k] : v[k + 8];
            float other = __shfl_xor_sync(FULL, send, 1);
            v[k] = (hi ? v[k + 8] : v[k]) + other;
        }
    }
    // step m=2: 8 -> 4
    {
        bool hi = (lane & 2);
#pragma unroll
        for (int k = 0; k < 4; k++) {
            float send  = hi ? v[k] : v[k + 4];
            float other = __shfl_xor_sync(FULL, send, 2);
            v[k] = (hi ? v[k + 4] : v[k]) + other;
        }
    }
    // step m=4: 4 -> 2
    {
        bool hi = (lane & 4);
#pragma unroll
        for (int k = 0; k < 2; k++) {
            float send  = hi ? v[k] : v[k + 2];
            float other = __shfl_xor_sync(FULL, send, 4);
            v[k] = (hi ? v[k + 2] : v[k]) + other;
        }
    }
    // step m=8: 2 -> 1
    {
        bool hi = (lane & 8);
        float send  = hi ? v[0] : v[1];
        float other = __shfl_xor_sync(FULL, send, 8);
        v[0] = (hi ? v[1] : v[0]) + other;
    }
    // final: reduce the two 16-lane halves
    v[0] += __shfl_xor_sync(FULL, v[0], 16);
    return v[0];
}

// ============ Kernel B: edge MLP + fused message aggregation ============
// Block: 256 threads = 256 consecutive j. Each block covers 8 i-rows.
// Grid: (4 j-tiles, 128 i-tiles).
__global__ __launch_bounds__(256, 2) void edge_kernel(const float* __restrict__ edges,
                                                      float* __restrict__ out_e) {
    __shared__ float s_pa[8 * 16];

    const int tid  = threadIdx.x;
    const int lane = tid & 31;
    const int j    = blockIdx.x * 256 + tid;
    const int i0   = blockIdx.y * 8;

    if (tid < 128) s_pa[tid] = g_pa[i0 * 16 + tid];

    // per-thread pb[j][0..15]
    float pb[16];
    {
        const float4* p4 = reinterpret_cast<const float4*>(g_pb + j * 16);
#pragma unroll
        for (int u = 0; u < 4; u++) {
            float4 v = p4[u];
            pb[u * 4 + 0] = v.x; pb[u * 4 + 1] = v.y;
            pb[u * 4 + 2] = v.z; pb[u * 4 + 3] = v.w;
        }
    }

    float msgb[16];
#pragma unroll
    for (int c = 0; c < 16; c++) msgb[c] = 0.0f;

    __syncthreads();

#pragma unroll 1
    for (int ir = 0; ir < 8; ir++) {
        const int i = i0 + ir;

        // load this edge's 32 features (8 x float4, MLP=8)
        const float4* xp = reinterpret_cast<const float4*>(edges + ((size_t)i * 1024 + j) * 32);
        float4 xv[8];
#pragma unroll
        for (int u = 0; u < 8; u++) xv[u] = xp[u];

        // layer 1: h = relu(pa[i] + pb[j] + edge @ We1[64:96])
        float h[16];
#pragma unroll
        for (int c = 0; c < 16; c++) h[c] = s_pa[ir * 16 + c] + pb[c];

#pragma unroll
        for (int u = 0; u < 8; u++) {
            const float4 v = xv[u];
            const int kb = 64 + u * 4;
#pragma unroll
            for (int c = 0; c < 16; c++) {
                h[c] = fmaf(v.x, cWe1[(kb + 0) * 16 + c], h[c]);
                h[c] = fmaf(v.y, cWe1[(kb + 1) * 16 + c], h[c]);
                h[c] = fmaf(v.z, cWe1[(kb + 2) * 16 + c], h[c]);
                h[c] = fmaf(v.w, cWe1[(kb + 3) * 16 + c], h[c]);
            }
        }
#pragma unroll
        for (int c = 0; c < 16; c++) h[c] = fmaxf(h[c], 0.0f);

        // layer 2: e2 = relu(h @ We2 + be2)
        float e2[16];
#pragma unroll
        for (int c = 0; c < 16; c++) e2[c] = cbe2[c];
#pragma unroll
        for (int k = 0; k < 16; k++) {
#pragma unroll
            for (int c = 0; c < 16; c++)
                e2[c] = fmaf(h[k], cWe2[k * 16 + c], e2[c]);
        }
#pragma unroll
        for (int c = 0; c < 16; c++) e2[c] = fmaxf(e2[c], 0.0f);

        // store new_edges[i][j][:]
        float4* op = reinterpret_cast<float4*>(out_e + ((size_t)i * 1024 + j) * 16);
#pragma unroll
        for (int u = 0; u < 4; u++)
            op[u] = make_float4(e2[u * 4 + 0], e2[u * 4 + 1], e2[u * 4 + 2], e2[u * 4 + 3]);

        // msg_b: register accumulate over the 8 i's
#pragma unroll
        for (int c = 0; c < 16; c++) msgb[c] += e2[c];

        // msg_a: butterfly channel-merge reduce across the warp (16 shfls),
        // then 16 lanes issue one atomicAdd each to distinct addresses.
        float total = warp_reduce16(e2, lane);
        if (lane < 16) atomicAdd(&g_msga[i * 16 + chan16(lane)], total);
    }

    // flush msg_b partials (distinct address per thread per c)
#pragma unroll
    for (int c = 0; c < 16; c++) atomicAdd(&g_msgb[j * 16 + c], msgb[c]);
}

// ============ Kernel C: node MLP for both node sets ============
__global__ __launch_bounds__(256) void node_kernel(const float* __restrict__ na,
                                                   const float* __restrict__ nb,
                                                   float* __restrict__ out_a,
                                                   float* __restrict__ out_b) {
    int r = blockIdx.x * blockDim.x + threadIdx.x;
    if (r >= 2 * N_NODES) return;

    const float* node;
    const float* msg;
    float* out;
    if (r < N_NODES) {
        node = na + r * 32;
        msg  = g_msga + r * 16;
        out  = out_a + r * 32;
    } else {
        int rr = r - N_NODES;
        node = nb + rr * 32;
        msg  = g_msgb + rr * 16;
        out  = out_b + rr * 32;
    }

    float x[48];
#pragma unroll
    for (int k = 0; k < 32; k++) x[k] = node[k];
#pragma unroll
    for (int k = 0; k < 16; k++) x[32 + k] = msg[k];

    float h[32];
#pragma unroll
    for (int c = 0; c < 32; c++) h[c] = cbn1[c];
#pragma unroll
    for (int k = 0; k < 48; k++) {
#pragma unroll
        for (int c = 0; c < 32; c++)
            h[c] = fmaf(x[k], cWn1[k * 32 + c], h[c]);
    }
#pragma unroll
    for (int c = 0; c < 32; c++) h[c] = fmaxf(h[c], 0.0f);

    float o[32];
#pragma unroll
    for (int c = 0; c < 32; c++) o[c] = cbn2[c];
#pragma unroll
    for (int k = 0; k < 32; k++) {
#pragma unroll
        for (int c = 0; c < 32; c++)
            o[c] = fmaf(h[k], cWn2[k * 32 + c], o[c]);
    }
#pragma unroll
    for (int c = 0; c < 32; c++) out[c] = fmaxf(o[c], 0.0f);
}

// ============ launch ============
extern "C" void kernel_launch(void* const* d_in, const int* in_sizes, int n_in,
                              void* d_out, int out_size) {
    const float* edges = (const float*)d_in[0];
    const float* na    = (const float*)d_in[1];
    const float* nb    = (const float*)d_in[2];

    // weights -> constant memory (D2D memcpys, graph-capturable)
    cudaMemcpyToSymbolAsync(cWe1, d_in[3], 96 * 16 * sizeof(float), 0, cudaMemcpyDeviceToDevice);
    cudaMemcpyToSymbolAsync(cbe1, d_in[4], 16 * sizeof(float),      0, cudaMemcpyDeviceToDevice);
    cudaMemcpyToSymbolAsync(cWe2, d_in[5], 16 * 16 * sizeof(float), 0, cudaMemcpyDeviceToDevice);
    cudaMemcpyToSymbolAsync(cbe2, d_in[6], 16 * sizeof(float),      0, cudaMemcpyDeviceToDevice);
    cudaMemcpyToSymbolAsync(cWn1, d_in[7], 48 * 32 * sizeof(float), 0, cudaMemcpyDeviceToDevice);
    cudaMemcpyToSymbolAsync(cbn1, d_in[8], 32 * sizeof(float),      0, cudaMemcpyDeviceToDevice);
    cudaMemcpyToSymbolAsync(cWn2, d_in[9], 32 * 32 * sizeof(float), 0, cudaMemcpyDeviceToDevice);
    cudaMemcpyToSymbolAsync(cbn2, d_in[10], 32 * sizeof(float),     0, cudaMemcpyDeviceToDevice);

    float* out_e = (float*)d_out;                       // (1024,1024,16)
    float* out_a = out_e + (size_t)1024 * 1024 * 16;    // (1024,32)
    float* out_b = out_a + 1024 * 32;                   // (1024,32)

    prep_kernel<<<4, 256>>>(na, nb);

    dim3 grid(4, 128);
    edge_kernel<<<grid, 256>>>(edges, out_e);

    node_kernel<<<8, 256>>>(na, nb, out_a, out_b);
}

// round 3
// speedup vs baseline: 1.0886x; 1.0886x over previous
#include <cuda_runtime.h>
#include <cuda_bf16.h>

#define N_NODES 1024
#define EDIM 16

typedef unsigned long long u64;

// ---------------- packed f32x2 helpers (sm_103a) ----------------
__device__ __forceinline__ u64 pack2(float lo, float hi) {
    u64 r; asm("mov.b64 %0, {%1, %2};" : "=l"(r) : "f"(lo), "f"(hi)); return r;
}
__device__ __forceinline__ void unpack2(u64 v, float& lo, float& hi) {
    asm("mov.b64 {%0, %1}, %2;" : "=f"(lo), "=f"(hi) : "l"(v));
}
__device__ __forceinline__ u64 ffma2(u64 a, u64 b, u64 c) {
    u64 d; asm("fma.rn.f32x2 %0, %1, %2, %3;" : "=l"(d) : "l"(a), "l"(b), "l"(c)); return d;
}

// ---------------- constant weights ----------------
__constant__ float cWe1[96 * 16];
__constant__ float cbe1[16];
__constant__ float cWe2[16 * 16];
__constant__ float cbe2[16];
__constant__ float cWn1[48 * 32];
__constant__ float cbn1[32];
__constant__ float cWn2[32 * 32];
__constant__ float cbn2[32];

// ---------------- device scratch ----------------
__device__ float g_pa[N_NODES * EDIM];
__device__ float g_pb[N_NODES * EDIM];
__device__ float g_msga[N_NODES * EDIM];
__device__ float g_msgb[N_NODES * EDIM];

// ============ Kernel A: zero accumulators + per-node precompute ============
// One thread per (node, channel): 16384 threads.
__global__ __launch_bounds__(256) void prep_kernel(const float* __restrict__ na,
                                                   const float* __restrict__ nb) {
    int t = blockIdx.x * blockDim.x + threadIdx.x;
    if (t >= N_NODES * EDIM) return;
    int node = t >> 4;
    int c    = t & 15;

    g_msga[t] = 0.0f;
    g_msgb[t] = 0.0f;

    float sa = cbe1[c];
    float sb = 0.0f;
    const float* arow = na + node * 32;
    const float* brow = nb + node * 32;
#pragma unroll
    for (int k = 0; k < 32; k++) {
        sa = fmaf(arow[k], cWe1[k * 16 + c], sa);
        sb = fmaf(brow[k], cWe1[(32 + k) * 16 + c], sb);
    }
    g_pa[t] = sa;
    g_pb[t] = sb;
}

// Butterfly channel-merging reduction: 16 channels x 32 lanes in 16 shfls.
__device__ __forceinline__ int chan16(int lane) {
    return ((lane & 1) ? 8 : 0) | ((lane & 2) ? 4 : 0) |
           ((lane & 4) ? 2 : 0) | ((lane & 8) ? 1 : 0);
}

__device__ __forceinline__ float warp_reduce16(float* v, int lane) {
    const unsigned FULL = 0xffffffffu;
    {
        bool hi = (lane & 1);
#pragma unroll
        for (int k = 0; k < 8; k++) {
            float send  = hi ? v[k] : v[k + 8];
            float other = __shfl_xor_sync(FULL, send, 1);
            v[k] = (hi ? v[k + 8] : v[k]) + other;
        }
    }
    {
        bool hi = (lane & 2);
#pragma unroll
        for (int k = 0; k < 4; k++) {
            float send  = hi ? v[k] : v[k + 4];
            float other = __shfl_xor_sync(FULL, send, 2);
            v[k] = (hi ? v[k + 4] : v[k]) + other;
        }
    }
    {
        bool hi = (lane & 4);
#pragma unroll
        for (int k = 0; k < 2; k++) {
            float send  = hi ? v[k] : v[k + 2];
            float other = __shfl_xor_sync(FULL, send, 4);
            v[k] = (hi ? v[k + 2] : v[k]) + other;
        }
    }
    {
        bool hi = (lane & 8);
        float send  = hi ? v[0] : v[1];
        float other = __shfl_xor_sync(FULL, send, 8);
        v[0] = (hi ? v[1] : v[0]) + other;
    }
    v[0] += __shfl_xor_sync(FULL, v[0], 16);
    return v[0];
}

// ============ Kernel B: edge MLP + fused message aggregation ============
// Block: 256 threads = 256 consecutive j; block covers 8 i-rows;
// each thread processes 2 i-rows at a time (weight reuse x2, f32x2 packed).
__global__ __launch_bounds__(256, 1) void edge_kernel(const float* __restrict__ edges,
                                                      float* __restrict__ out_e) {
    __shared__ float s_pa[8 * 16];

    const int tid  = threadIdx.x;
    const int lane = tid & 31;
    const int j    = blockIdx.x * 256 + tid;
    const int i0   = blockIdx.y * 8;

    if (tid < 128) s_pa[tid] = g_pa[i0 * 16 + tid];

    const u64* cWe1p = reinterpret_cast<const u64*>(cWe1);
    const u64* cWe2p = reinterpret_cast<const u64*>(cWe2);

    float pb[16];
    {
        const float4* p4 = reinterpret_cast<const float4*>(g_pb + j * 16);
#pragma unroll
        for (int u = 0; u < 4; u++) {
            float4 v = p4[u];
            pb[u * 4 + 0] = v.x; pb[u * 4 + 1] = v.y;
            pb[u * 4 + 2] = v.z; pb[u * 4 + 3] = v.w;
        }
    }

    u64 be2p[8];
#pragma unroll
    for (int p = 0; p < 8; p++) be2p[p] = pack2(cbe2[2 * p], cbe2[2 * p + 1]);

    float msgb[16];
#pragma unroll
    for (int c = 0; c < 16; c++) msgb[c] = 0.0f;

    __syncthreads();

#pragma unroll 1
    for (int ir2 = 0; ir2 < 4; ir2++) {
        const int r0 = ir2 * 2;
        const int r1 = r0 + 1;
        const int i  = i0 + r0;

        const float* base0 = edges + ((size_t)i * 1024 + j) * 32;
        const float* base1 = base0 + 32768;   // next i-row

        // ---- layer 1: packed accumulators over channel pairs ----
        u64 h2[2][8];
#pragma unroll
        for (int p = 0; p < 8; p++) {
            h2[0][p] = pack2(s_pa[r0 * 16 + 2 * p] + pb[2 * p],
                             s_pa[r0 * 16 + 2 * p + 1] + pb[2 * p + 1]);
            h2[1][p] = pack2(s_pa[r1 * 16 + 2 * p] + pb[2 * p],
                             s_pa[r1 * 16 + 2 * p + 1] + pb[2 * p + 1]);
        }

#pragma unroll
        for (int u = 0; u < 8; u++) {
            float4 x0 = *reinterpret_cast<const float4*>(base0 + u * 4);
            float4 x1 = *reinterpret_cast<const float4*>(base1 + u * 4);
            u64 a0[4] = { pack2(x0.x, x0.x), pack2(x0.y, x0.y),
                          pack2(x0.z, x0.z), pack2(x0.w, x0.w) };
            u64 a1[4] = { pack2(x1.x, x1.x), pack2(x1.y, x1.y),
                          pack2(x1.z, x1.z), pack2(x1.w, x1.w) };
#pragma unroll
            for (int kk = 0; kk < 4; kk++) {
                const ulonglong2* w2 =
                    reinterpret_cast<const ulonglong2*>(cWe1p + (64 + u * 4 + kk) * 8);
#pragma unroll
                for (int q = 0; q < 4; q++) {
                    ulonglong2 w = w2[q];
                    h2[0][2 * q]     = ffma2(a0[kk], w.x, h2[0][2 * q]);
                    h2[0][2 * q + 1] = ffma2(a0[kk], w.y, h2[0][2 * q + 1]);
                    h2[1][2 * q]     = ffma2(a1[kk], w.x, h2[1][2 * q]);
                    h2[1][2 * q + 1] = ffma2(a1[kk], w.y, h2[1][2 * q + 1]);
                }
            }
        }

        // relu + unpack h
        float h[2][16];
#pragma unroll
        for (int r = 0; r < 2; r++)
#pragma unroll
            for (int p = 0; p < 8; p++) {
                float lo, hi; unpack2(h2[r][p], lo, hi);
                h[r][2 * p]     = fmaxf(lo, 0.0f);
                h[r][2 * p + 1] = fmaxf(hi, 0.0f);
            }

        // ---- layer 2 ----
        u64 e2p[2][8];
#pragma unroll
        for (int p = 0; p < 8; p++) { e2p[0][p] = be2p[p]; e2p[1][p] = be2p[p]; }

#pragma unroll
        for (int k = 0; k < 16; k++) {
            u64 a0 = pack2(h[0][k], h[0][k]);
            u64 a1 = pack2(h[1][k], h[1][k]);
            const ulonglong2* w2 = reinterpret_cast<const ulonglong2*>(cWe2p + k * 8);
#pragma unroll
            for (int q = 0; q < 4; q++) {
                ulonglong2 w = w2[q];
                e2p[0][2 * q]     = ffma2(a0, w.x, e2p[0][2 * q]);
                e2p[0][2 * q + 1] = ffma2(a0, w.y, e2p[0][2 * q + 1]);
                e2p[1][2 * q]     = ffma2(a1, w.x, e2p[1][2 * q]);
                e2p[1][2 * q + 1] = ffma2(a1, w.y, e2p[1][2 * q + 1]);
            }
        }

        // relu, store, aggregate
#pragma unroll
        for (int r = 0; r < 2; r++) {
            float e[16];
#pragma unroll
            for (int p = 0; p < 8; p++) {
                float lo, hi; unpack2(e2p[r][p], lo, hi);
                e[2 * p]     = fmaxf(lo, 0.0f);
                e[2 * p + 1] = fmaxf(hi, 0.0f);
            }

            float4* op = reinterpret_cast<float4*>(out_e + ((size_t)(i + r) * 1024 + j) * 16);
#pragma unroll
            for (int qq = 0; qq < 4; qq++)
                op[qq] = make_float4(e[4 * qq], e[4 * qq + 1], e[4 * qq + 2], e[4 * qq + 3]);

#pragma unroll
            for (int c = 0; c < 16; c++) msgb[c] += e[c];

            float total = warp_reduce16(e, lane);
            if (lane < 16) atomicAdd(&g_msga[(i + r) * 16 + chan16(lane)], total);
        }
    }

#pragma unroll
    for (int c = 0; c < 16; c++) atomicAdd(&g_msgb[j * 16 + c], msgb[c]);
}

// ============ Kernel C: node MLP for both node sets ============
__global__ __launch_bounds__(256) void node_kernel(const float* __restrict__ na,
                                                   const float* __restrict__ nb,
                                                   float* __restrict__ out_a,
                                                   float* __restrict__ out_b) {
    int r = blockIdx.x * blockDim.x + threadIdx.x;
    if (r >= 2 * N_NODES) return;

    const float* node;
    const float* msg;
    float* out;
    if (r < N_NODES) {
        node = na + r * 32;
        msg  = g_msga + r * 16;
        out  = out_a + r * 32;
    } else {
        int rr = r - N_NODES;
        node = nb + rr * 32;
        msg  = g_msgb + rr * 16;
        out  = out_b + rr * 32;
    }

    float x[48];
#pragma unroll
    for (int k = 0; k < 32; k++) x[k] = node[k];
#pragma unroll
    for (int k = 0; k < 16; k++) x[32 + k] = msg[k];

    float h[32];
#pragma unroll
    for (int c = 0; c < 32; c++) h[c] = cbn1[c];
#pragma unroll
    for (int k = 0; k < 48; k++) {
#pragma unroll
        for (int c = 0; c < 32; c++)
            h[c] = fmaf(x[k], cWn1[k * 32 + c], h[c]);
    }
#pragma unroll
    for (int c = 0; c < 32; c++) h[c] = fmaxf(h[c], 0.0f);

    float o[32];
#pragma unroll
    for (int c = 0; c < 32; c++) o[c] = cbn2[c];
#pragma unroll
    for (int k = 0; k < 32; k++) {
#pragma unroll
        for (int c = 0; c < 32; c++)
            o[c] = fmaf(h[k], cWn2[k * 32 + c], o[c]);
    }
#pragma unroll
    for (int c = 0; c < 32; c++) out[c] = fmaxf(o[c], 0.0f);
}

// ============ launch ============
extern "C" void kernel_launch(void* const* d_in, const int* in_sizes, int n_in,
                              void* d_out, int out_size) {
    const float* edges = (const float*)d_in[0];
    const float* na    = (const float*)d_in[1];
    const float* nb    = (const float*)d_in[2];

    cudaMemcpyToSymbolAsync(cWe1, d_in[3], 96 * 16 * sizeof(float), 0, cudaMemcpyDeviceToDevice);
    cudaMemcpyToSymbolAsync(cbe1, d_in[4], 16 * sizeof(float),      0, cudaMemcpyDeviceToDevice);
    cudaMemcpyToSymbolAsync(cWe2, d_in[5], 16 * 16 * sizeof(float), 0, cudaMemcpyDeviceToDevice);
    cudaMemcpyToSymbolAsync(cbe2, d_in[6], 16 * sizeof(float),      0, cudaMemcpyDeviceToDevice);
    cudaMemcpyToSymbolAsync(cWn1, d_in[7], 48 * 32 * sizeof(float), 0, cudaMemcpyDeviceToDevice);
    cudaMemcpyToSymbolAsync(cbn1, d_in[8], 32 * sizeof(float),      0, cudaMemcpyDeviceToDevice);
    cudaMemcpyToSymbolAsync(cWn2, d_in[9], 32 * 32 * sizeof(float), 0, cudaMemcpyDeviceToDevice);
    cudaMemcpyToSymbolAsync(cbn2, d_in[10], 32 * sizeof(float),     0, cudaMemcpyDeviceToDevice);

    float* out_e = (float*)d_out;
    float* out_a = out_e + (size_t)1024 * 1024 * 16;
    float* out_b = out_a + 1024 * 32;

    prep_kernel<<<(N_NODES * EDIM + 255) / 256, 256>>>(na, nb);

    dim3 grid(4, 128);
    edge_kernel<<<grid, 256>>>(edges, out_e);

    node_kernel<<<8, 256>>>(na, nb, out_a, out_b);
}